// round 1
// baseline (speedup 1.0000x reference)
#include <cuda_runtime.h>
#include <cuda_bf16.h>

// Problem constants
#define TT   64
#define WW   88
#define HPc  48
#define CIN  53        // HP + 4 (emb) + 1 (mask)
#define HLc  12
#define G4   48        // 4*HL gates per direction
#define NHh  4
#define HDd  6
#define NUc  24
#define KK   25
#define NPX  (TT*WW)   // 5632

// Scratch buffers (device globals — no allocation allowed)
__device__ float g_x0[NPX*NUc];
__device__ float g_x1[NPX*NUc];
__device__ float g_q [NPX*NUc];
__device__ float g_k [NPX*NUc];
__device__ float g_v [NPX*NUc];

__device__ __forceinline__ float sigf(float x) {
    return 1.0f / (1.0f + __expf(-x));
}

// ---------------------------------------------------------------------------
// Fused: input build + bidirectional LSTM layer 0 + layer 1.
// One block per sequence (w). 96 threads = 2 dirs x 48 gates.
// Writes g_x0 laid out [t][w][24]  (fwd hidden 0..11, bwd hidden 12..23)
// ---------------------------------------------------------------------------
__global__ void __launch_bounds__(96)
lstm_kernel(const float* __restrict__ features,   // (1,64,48,88)
            const int*   __restrict__ condition,  // (1,64,88)
            const float* __restrict__ mask,       // (1,64,88)
            const float* __restrict__ emb,        // (5,4)
            const float* __restrict__ wih0,       // (2,48,53)
            const float* __restrict__ whh0,       // (2,48,12)
            const float* __restrict__ bih0,       // (2,48)
            const float* __restrict__ bhh0,       // (2,48)
            const float* __restrict__ wih1,       // (2,48,24)
            const float* __restrict__ whh1,       // (2,48,12)
            const float* __restrict__ bih1,       // (2,48)
            const float* __restrict__ bhh1)       // (2,48)
{
    const int w   = blockIdx.x;
    const int tid = threadIdx.x;          // 0..95
    const int dir = tid / G4;             // 0 fwd, 1 bwd
    const int g   = tid % G4;             // gate index 0..47
    const int u   = g % HLc;              // hidden unit (valid when g<12)

    __shared__ float xs  [TT][CIN];       // 13.6 KB
    __shared__ float preg[TT][96];        // 24.6 KB
    __shared__ float hbuf[TT][2*HLc];     // 6.1 KB  (layer-0 output)
    __shared__ float hcur[2][HLc];
    __shared__ float ccur[2][HLc];

    // ---- build input sequence ----
    for (int idx = tid; idx < TT*CIN; idx += 96) {
        int t = idx / CIN, c = idx % CIN;
        float val;
        if (c < HPc)            val = features[(t*HPc + c)*WW + w];
        else if (c < HPc + 4)   val = emb[condition[t*WW + w]*4 + (c - HPc)];
        else                    val = mask[t*WW + w];
        xs[t][c] = val;
    }
    __syncthreads();

    // ---- phase 1: layer-0 pre-gates (no recurrence, full ILP) ----
    {
        float wr[CIN];
        const float* wrow = wih0 + (dir*G4 + g)*CIN;
        #pragma unroll
        for (int c = 0; c < CIN; c++) wr[c] = wrow[c];
        const float b = bih0[dir*G4 + g] + bhh0[dir*G4 + g];
        for (int t = 0; t < TT; t++) {
            float acc = b;
            #pragma unroll
            for (int c = 0; c < CIN; c++) acc = fmaf(xs[t][c], wr[c], acc);
            preg[t][tid] = acc;
        }
    }
    if (g < HLc) { hcur[dir][u] = 0.f; ccur[dir][u] = 0.f; }
    __syncthreads();

    // ---- phase 2: layer-0 recurrence ----
    {
        float wr[HLc];
        const float* wrow = whh0 + (dir*G4 + g)*HLc;
        #pragma unroll
        for (int c = 0; c < HLc; c++) wr[c] = wrow[c];
        for (int s = 0; s < TT; s++) {
            const int t = dir ? (TT - 1 - s) : s;
            float acc = preg[t][tid];
            #pragma unroll
            for (int c = 0; c < HLc; c++) acc = fmaf(hcur[dir][c], wr[c], acc);
            preg[t][tid] = acc;
            __syncthreads();
            if (g < HLc) {
                float gi = preg[t][dir*G4 +      u];
                float gf = preg[t][dir*G4 + 12 + u];
                float gg = preg[t][dir*G4 + 24 + u];
                float go = preg[t][dir*G4 + 36 + u];
                float cn = sigf(gf)*ccur[dir][u] + sigf(gi)*tanhf(gg);
                float hn = sigf(go)*tanhf(cn);
                ccur[dir][u] = cn;
                hcur[dir][u] = hn;
                hbuf[t][dir*HLc + u] = hn;
            }
            __syncthreads();
        }
    }

    // ---- phase 3: layer-1 pre-gates ----
    {
        float wr[2*HLc];
        const float* wrow = wih1 + (dir*G4 + g)*(2*HLc);
        #pragma unroll
        for (int c = 0; c < 2*HLc; c++) wr[c] = wrow[c];
        const float b = bih1[dir*G4 + g] + bhh1[dir*G4 + g];
        for (int t = 0; t < TT; t++) {
            float acc = b;
            #pragma unroll
            for (int c = 0; c < 2*HLc; c++) acc = fmaf(hbuf[t][c], wr[c], acc);
            preg[t][tid] = acc;
        }
    }
    if (g < HLc) { hcur[dir][u] = 0.f; ccur[dir][u] = 0.f; }
    __syncthreads();

    // ---- phase 4: layer-1 recurrence, write transposed to g_x0[t][w][ch] ----
    {
        float wr[HLc];
        const float* wrow = whh1 + (dir*G4 + g)*HLc;
        #pragma unroll
        for (int c = 0; c < HLc; c++) wr[c] = wrow[c];
        for (int s = 0; s < TT; s++) {
            const int t = dir ? (TT - 1 - s) : s;
            float acc = preg[t][tid];
            #pragma unroll
            for (int c = 0; c < HLc; c++) acc = fmaf(hcur[dir][c], wr[c], acc);
            preg[t][tid] = acc;
            __syncthreads();
            if (g < HLc) {
                float gi = preg[t][dir*G4 +      u];
                float gf = preg[t][dir*G4 + 12 + u];
                float gg = preg[t][dir*G4 + 24 + u];
                float go = preg[t][dir*G4 + 36 + u];
                float cn = sigf(gf)*ccur[dir][u] + sigf(gi)*tanhf(gg);
                float hn = sigf(go)*tanhf(cn);
                ccur[dir][u] = cn;
                hcur[dir][u] = hn;
                g_x0[(t*WW + w)*NUc + dir*HLc + u] = hn;
            }
            __syncthreads();
        }
    }
}

// ---------------------------------------------------------------------------
// QKV projection: per (pixel, out-channel) dot of 24.
// ---------------------------------------------------------------------------
__global__ void __launch_bounds__(256)
qkv_kernel(const float* __restrict__ x,
           const float* __restrict__ qw,   // (72,24)
           const float* __restrict__ qb)   // (72,)
{
    int idx = blockIdx.x*blockDim.x + threadIdx.x;
    if (idx >= NPX*72) return;
    int px = idx / 72, oc = idx % 72;
    const float* xr = x + px*NUc;
    const float* wr = qw + oc*NUc;
    float acc = __ldg(qb + oc);
    #pragma unroll
    for (int c = 0; c < NUc; c++) acc = fmaf(__ldg(xr + c), __ldg(wr + c), acc);
    int e = oc / NUc, ch = oc % NUc;
    if      (e == 0) g_q[px*NUc + ch] = acc * 0.4082482904638631f; // HD^-0.5
    else if (e == 1) g_k[px*NUc + ch] = acc;
    else             g_v[px*NUc + ch] = acc;
}

// ---------------------------------------------------------------------------
// NATTEN-2D + output projection.
// Block = row i, 8 columns, 4 heads -> 32 warps, one warp per (pixel, head).
// K/V window (25 x <=32 px x 24 ch) staged in dynamic shared memory.
// ---------------------------------------------------------------------------
__global__ void __launch_bounds__(1024)
natten_kernel(const float* __restrict__ rpb,   // (4,49,49)
              const float* __restrict__ pw,    // (24,24)
              const float* __restrict__ pb,    // (24,)
              float* __restrict__ out)         // (64,88,24)
{
    const int i  = blockIdx.y;
    const int j0 = blockIdx.x * 8;
    extern __shared__ float sm[];
    float* ks = sm;                 // [25][32][24]
    float* vs = sm + 25*32*24;      // [25][32][24]
    float* ao = vs + 25*32*24;      // [8][24]

    const int si      = min(max(i  - 12, 0), TT - KK);        // row window start
    const int sj_min  = min(max(j0 - 12, 0), WW - KK);
    const int sj_last = min(max(j0 + 7 - 12, 0), WW - KK);
    const int ncols   = sj_last + KK - sj_min;                 // <= 32

    const int tid = threadIdx.x;

    // stage K/V window (float4 vectorized)
    const int npx = KK * ncols;
    for (int idx = tid; idx < npx*6; idx += 1024) {
        int px = idx / 6, f4 = idx % 6;
        int a = px / ncols, c = px % ncols;
        int gpx = (si + a)*WW + (sj_min + c);
        float4 kd = *(const float4*)(g_k + gpx*NUc + f4*4);
        float4 vd = *(const float4*)(g_v + gpx*NUc + f4*4);
        int spx = a*32 + c;
        *(float4*)(ks + spx*NUc + f4*4) = kd;
        *(float4*)(vs + spx*NUc + f4*4) = vd;
    }
    __syncthreads();

    const int warp = tid / 32, lane = tid % 32;
    const int p = warp / NHh;          // pixel within tile 0..7
    const int n = warp % NHh;          // head
    const int j = j0 + p;
    const int sj = min(max(j - 12, 0), WW - KK);
    const int colbase = sj - sj_min;   // 0..7
    const int ra0 = si - i + (KK - 1);
    const int rc0 = sj - j + (KK - 1);
    const float* rp = rpb + n*49*49;

    float qr[HDd];
    {
        const float* qp = g_q + ((i*WW + j)*NUc + n*HDd);
        #pragma unroll
        for (int d = 0; d < HDd; d++) qr[d] = qp[d];
    }

    // pass 1: logits (+rpb), track max. 625 neighbors strided across lanes.
    float lg[20];
    float lmax = -1e30f;
    #pragma unroll
    for (int e0 = 0; e0 < 20; e0++) {
        int e = lane + e0*32;
        if (e < KK*KK) {
            int a = e / KK, c = e % KK;
            const float* kp = ks + (a*32 + colbase + c)*NUc + n*HDd;
            float acc = __ldg(rp + (ra0 + a)*49 + (rc0 + c));
            #pragma unroll
            for (int d = 0; d < HDd; d++) acc = fmaf(qr[d], kp[d], acc);
            lg[e0] = acc;
            lmax = fmaxf(lmax, acc);
        } else {
            lg[e0] = -1e30f;
        }
    }
    #pragma unroll
    for (int o = 16; o > 0; o >>= 1)
        lmax = fmaxf(lmax, __shfl_xor_sync(0xffffffffu, lmax, o));

    // pass 2: exp + weighted V accumulation
    float sum = 0.f;
    float oacc[HDd] = {0.f,0.f,0.f,0.f,0.f,0.f};
    #pragma unroll
    for (int e0 = 0; e0 < 20; e0++) {
        int e = lane + e0*32;
        if (e < KK*KK) {
            float pr = __expf(lg[e0] - lmax);
            sum += pr;
            int a = e / KK, c = e % KK;
            const float* vp = vs + (a*32 + colbase + c)*NUc + n*HDd;
            #pragma unroll
            for (int d = 0; d < HDd; d++) oacc[d] = fmaf(pr, vp[d], oacc[d]);
        }
    }
    #pragma unroll
    for (int o = 16; o > 0; o >>= 1) {
        sum += __shfl_xor_sync(0xffffffffu, sum, o);
        #pragma unroll
        for (int d = 0; d < HDd; d++)
            oacc[d] += __shfl_xor_sync(0xffffffffu, oacc[d], o);
    }
    if (lane == 0) {
        float inv = 1.0f / sum;
        #pragma unroll
        for (int d = 0; d < HDd; d++) ao[p*NUc + n*HDd + d] = oacc[d]*inv;
    }
    __syncthreads();

    // fused output projection (24x24) : 8 px * 24 oc = 192 threads
    if (tid < 8*NUc) {
        int pp = tid / NUc, oc = tid % NUc;
        float acc = __ldg(pb + oc);
        const float* wrow = pw + oc*NUc;
        #pragma unroll
        for (int ic = 0; ic < NUc; ic++)
            acc = fmaf(ao[pp*NUc + ic], __ldg(wrow + ic), acc);
        out[(i*WW + j0 + pp)*NUc + oc] = acc;
    }
}

// ---------------------------------------------------------------------------
// Final head: (24 -> 5) per pixel
// ---------------------------------------------------------------------------
__global__ void __launch_bounds__(128)
head_kernel(const float* __restrict__ x,
            const float* __restrict__ ow,   // (5,24)
            const float* __restrict__ ob,   // (5,)
            float* __restrict__ out)        // (64,88,5)
{
    int idx = blockIdx.x*blockDim.x + threadIdx.x;
    if (idx >= NPX*5) return;
    int px = idx / 5, oc = idx % 5;
    float acc = __ldg(ob + oc);
    const float* xr = x + px*NUc;
    const float* wr = ow + oc*NUc;
    #pragma unroll
    for (int c = 0; c < NUc; c++) acc = fmaf(__ldg(xr + c), __ldg(wr + c), acc);
    out[idx] = acc;
}

// ---------------------------------------------------------------------------
extern "C" void kernel_launch(void* const* d_in, const int* in_sizes, int n_in,
                              void* d_out, int out_size)
{
    const float* features  = (const float*)d_in[0];
    const int*   condition = (const int*)  d_in[1];
    const float* mask      = (const float*)d_in[2];
    const float* emb       = (const float*)d_in[3];
    const float* wih0      = (const float*)d_in[4];
    const float* whh0      = (const float*)d_in[5];
    const float* bih0      = (const float*)d_in[6];
    const float* bhh0      = (const float*)d_in[7];
    const float* wih1      = (const float*)d_in[8];
    const float* whh1      = (const float*)d_in[9];
    const float* bih1      = (const float*)d_in[10];
    const float* bhh1      = (const float*)d_in[11];
    const float* qkv_w     = (const float*)d_in[12];
    const float* qkv_b     = (const float*)d_in[13];
    const float* rpb       = (const float*)d_in[14];
    const float* proj_w    = (const float*)d_in[15];
    const float* proj_b    = (const float*)d_in[16];
    const float* out_w     = (const float*)d_in[17];
    const float* out_b     = (const float*)d_in[18];
    float* out = (float*)d_out;

    // resolve scratch buffer addresses (device globals)
    float *px0 = nullptr, *px1 = nullptr;
    cudaGetSymbolAddress((void**)&px0, g_x0);
    cudaGetSymbolAddress((void**)&px1, g_x1);

    const int natten_smem = (2*25*32*24 + 8*24) * (int)sizeof(float); // 154368 B
    cudaFuncSetAttribute(natten_kernel,
                         cudaFuncAttributeMaxDynamicSharedMemorySize, natten_smem);

    // 1) fused LSTM (input build + 2 bidirectional layers) -> g_x0
    lstm_kernel<<<WW, 96>>>(features, condition, mask, emb,
                            wih0, whh0, bih0, bhh0,
                            wih1, whh1, bih1, bhh1);

    dim3 ngrid(WW/8, TT);

    // 2) NATTEN layer 1: g_x0 -> qkv -> attn+proj -> g_x1
    qkv_kernel<<<(NPX*72 + 255)/256, 256>>>(px0, qkv_w, qkv_b);
    natten_kernel<<<ngrid, 1024, natten_smem>>>(rpb, proj_w, proj_b, px1);

    // 3) NATTEN layer 2: g_x1 -> qkv -> attn+proj -> g_x0
    qkv_kernel<<<(NPX*72 + 255)/256, 256>>>(px1, qkv_w, qkv_b);
    natten_kernel<<<ngrid, 1024, natten_smem>>>(rpb, proj_w, proj_b, px0);

    // 4) head: g_x0 -> out
    head_kernel<<<(NPX*5 + 127)/128, 128>>>(px0, out_w, out_b, out);
}

// round 2
// speedup vs baseline: 1.4438x; 1.4438x over previous
#include <cuda_runtime.h>
#include <cuda_bf16.h>

// Problem constants
#define TT   64
#define WW   88
#define HPc  48
#define CIN  53        // HP + 4 (emb) + 1 (mask)
#define HLc  12
#define G4   48        // 4*HL gates per direction
#define NHh  4
#define HDd  6
#define NUc  24
#define KK   25
#define NPX  (TT*WW)   // 5632
#define PITCH 25       // padded smem pixel pitch (odd -> conflict-free)

// Scratch buffers (device globals — no allocation allowed)
__device__ float g_x0[NPX*NUc];
__device__ float g_x1[NPX*NUc];
__device__ float g_q [NPX*NUc];
__device__ float g_k [NPX*NUc];
__device__ float g_v [NPX*NUc];

__device__ __forceinline__ float sigf(float x) {
    return 1.0f / (1.0f + __expf(-x));
}

// ---------------------------------------------------------------------------
// Fused: input build + bidirectional LSTM layer 0 + layer 1.
// One block per sequence (w). 96 threads = 2 dirs x 48 gates.
// ---------------------------------------------------------------------------
__global__ void __launch_bounds__(96)
lstm_kernel(const float* __restrict__ features,   // (1,64,48,88)
            const int*   __restrict__ condition,  // (1,64,88)
            const float* __restrict__ mask,       // (1,64,88)
            const float* __restrict__ emb,        // (5,4)
            const float* __restrict__ wih0,       // (2,48,53)
            const float* __restrict__ whh0,       // (2,48,12)
            const float* __restrict__ bih0,       // (2,48)
            const float* __restrict__ bhh0,       // (2,48)
            const float* __restrict__ wih1,       // (2,48,24)
            const float* __restrict__ whh1,       // (2,48,12)
            const float* __restrict__ bih1,       // (2,48)
            const float* __restrict__ bhh1)       // (2,48)
{
    const int w   = blockIdx.x;
    const int tid = threadIdx.x;          // 0..95
    const int dir = tid / G4;             // 0 fwd, 1 bwd
    const int g   = tid % G4;             // gate index 0..47
    const int u   = g % HLc;              // hidden unit (valid when g<12)

    __shared__ float xs  [TT][CIN];
    __shared__ float preg[TT][96];
    __shared__ float hbuf[TT][2*HLc];
    __shared__ float hcur[2][HLc];
    __shared__ float ccur[2][HLc];

    // ---- build input sequence ----
    for (int idx = tid; idx < TT*CIN; idx += 96) {
        int t = idx / CIN, c = idx % CIN;
        float val;
        if (c < HPc)            val = features[(t*HPc + c)*WW + w];
        else if (c < HPc + 4)   val = emb[condition[t*WW + w]*4 + (c - HPc)];
        else                    val = mask[t*WW + w];
        xs[t][c] = val;
    }
    __syncthreads();

    // ---- phase 1: layer-0 pre-gates ----
    {
        float wr[CIN];
        const float* wrow = wih0 + (dir*G4 + g)*CIN;
        #pragma unroll
        for (int c = 0; c < CIN; c++) wr[c] = wrow[c];
        const float b = bih0[dir*G4 + g] + bhh0[dir*G4 + g];
        for (int t = 0; t < TT; t++) {
            float acc = b;
            #pragma unroll
            for (int c = 0; c < CIN; c++) acc = fmaf(xs[t][c], wr[c], acc);
            preg[t][tid] = acc;
        }
    }
    if (g < HLc) { hcur[dir][u] = 0.f; ccur[dir][u] = 0.f; }
    __syncthreads();

    // ---- phase 2: layer-0 recurrence ----
    {
        float wr[HLc];
        const float* wrow = whh0 + (dir*G4 + g)*HLc;
        #pragma unroll
        for (int c = 0; c < HLc; c++) wr[c] = wrow[c];
        for (int s = 0; s < TT; s++) {
            const int t = dir ? (TT - 1 - s) : s;
            float acc = preg[t][tid];
            #pragma unroll
            for (int c = 0; c < HLc; c++) acc = fmaf(hcur[dir][c], wr[c], acc);
            preg[t][tid] = acc;
            __syncthreads();
            if (g < HLc) {
                float gi = preg[t][dir*G4 +      u];
                float gf = preg[t][dir*G4 + 12 + u];
                float gg = preg[t][dir*G4 + 24 + u];
                float go = preg[t][dir*G4 + 36 + u];
                float cn = sigf(gf)*ccur[dir][u] + sigf(gi)*tanhf(gg);
                float hn = sigf(go)*tanhf(cn);
                ccur[dir][u] = cn;
                hcur[dir][u] = hn;
                hbuf[t][dir*HLc + u] = hn;
            }
            __syncthreads();
        }
    }

    // ---- phase 3: layer-1 pre-gates ----
    {
        float wr[2*HLc];
        const float* wrow = wih1 + (dir*G4 + g)*(2*HLc);
        #pragma unroll
        for (int c = 0; c < 2*HLc; c++) wr[c] = wrow[c];
        const float b = bih1[dir*G4 + g] + bhh1[dir*G4 + g];
        for (int t = 0; t < TT; t++) {
            float acc = b;
            #pragma unroll
            for (int c = 0; c < 2*HLc; c++) acc = fmaf(hbuf[t][c], wr[c], acc);
            preg[t][tid] = acc;
        }
    }
    if (g < HLc) { hcur[dir][u] = 0.f; ccur[dir][u] = 0.f; }
    __syncthreads();

    // ---- phase 4: layer-1 recurrence ----
    {
        float wr[HLc];
        const float* wrow = whh1 + (dir*G4 + g)*HLc;
        #pragma unroll
        for (int c = 0; c < HLc; c++) wr[c] = wrow[c];
        for (int s = 0; s < TT; s++) {
            const int t = dir ? (TT - 1 - s) : s;
            float acc = preg[t][tid];
            #pragma unroll
            for (int c = 0; c < HLc; c++) acc = fmaf(hcur[dir][c], wr[c], acc);
            preg[t][tid] = acc;
            __syncthreads();
            if (g < HLc) {
                float gi = preg[t][dir*G4 +      u];
                float gf = preg[t][dir*G4 + 12 + u];
                float gg = preg[t][dir*G4 + 24 + u];
                float go = preg[t][dir*G4 + 36 + u];
                float cn = sigf(gf)*ccur[dir][u] + sigf(gi)*tanhf(gg);
                float hn = sigf(go)*tanhf(cn);
                ccur[dir][u] = cn;
                hcur[dir][u] = hn;
                g_x0[(t*WW + w)*NUc + dir*HLc + u] = hn;
            }
            __syncthreads();
        }
    }
}

// ---------------------------------------------------------------------------
// QKV projection: one thread per (e, pixel); weights broadcast from shared.
// grid: 66 blocks x 256 threads = 16896 = 3 * NPX exactly.
// ---------------------------------------------------------------------------
__global__ void __launch_bounds__(256)
qkv_kernel(const float* __restrict__ x,
           const float* __restrict__ qw,   // (72,24)
           const float* __restrict__ qb)   // (72,)
{
    __shared__ float wsh[72*24];
    __shared__ float bsh[72];
    const int tid = threadIdx.x;
    for (int i = tid; i < 72*24; i += 256) wsh[i] = qw[i];
    if (tid < 72) bsh[tid] = qb[tid];
    __syncthreads();

    const int idx = blockIdx.x*256 + tid;       // < 3*NPX always (66*256)
    const int e  = idx / NPX;                    // 0=q,1=k,2=v (warp-uniform)
    const int px = idx % NPX;

    float xr[NUc];
    const float4* xp = (const float4*)(x + px*NUc);
    #pragma unroll
    for (int f = 0; f < 6; f++) {
        float4 t = xp[f];
        xr[f*4+0]=t.x; xr[f*4+1]=t.y; xr[f*4+2]=t.z; xr[f*4+3]=t.w;
    }

    float acc[NUc];
    #pragma unroll
    for (int oc = 0; oc < NUc; oc++) acc[oc] = bsh[e*NUc + oc];
    #pragma unroll
    for (int c = 0; c < NUc; c++) {
        float xv = xr[c];
        #pragma unroll
        for (int oc = 0; oc < NUc; oc++)
            acc[oc] = fmaf(xv, wsh[(e*NUc + oc)*NUc + c], acc[oc]);
    }

    float scale = (e == 0) ? 0.4082482904638631f : 1.0f;
    float* dst = (e == 0) ? g_q : (e == 1) ? g_k : g_v;
    float4* dp = (float4*)(dst + px*NUc);
    #pragma unroll
    for (int f = 0; f < 6; f++) {
        float4 t;
        t.x = acc[f*4+0]*scale; t.y = acc[f*4+1]*scale;
        t.z = acc[f*4+2]*scale; t.w = acc[f*4+3]*scale;
        dp[f] = t;
    }
}

// ---------------------------------------------------------------------------
// NATTEN-2D + output projection. Padded smem (PITCH=25) -> no bank conflicts.
// Block = row i, 8 columns, 4 heads -> 32 warps, one warp per (pixel, head).
// ---------------------------------------------------------------------------
__global__ void __launch_bounds__(1024)
natten_kernel(const float* __restrict__ rpb,   // (4,49,49)
              const float* __restrict__ pw,    // (24,24)
              const float* __restrict__ pb,    // (24,)
              float* __restrict__ out)         // (64,88,24)
{
    const int i  = blockIdx.y;
    const int j0 = blockIdx.x * 8;
    extern __shared__ float sm[];
    float* ks = sm;                        // [25*32][PITCH]
    float* vs = sm + KK*32*PITCH;          // [25*32][PITCH]
    float* ao = vs + KK*32*PITCH;          // [8][24]

    const int si      = min(max(i  - 12, 0), TT - KK);
    const int sj_min  = min(max(j0 - 12, 0), WW - KK);
    const int sj_last = min(max(j0 + 7 - 12, 0), WW - KK);
    const int ncols   = sj_last + KK - sj_min;                 // <= 32

    const int tid = threadIdx.x;

    // stage K/V window: float4 global reads, scalar padded smem writes
    const int npx = KK * ncols;
    for (int idx = tid; idx < npx*6; idx += 1024) {
        int px = idx / 6, f4 = idx % 6;
        int a = px / ncols, c = px % ncols;
        int gpx = (si + a)*WW + (sj_min + c);
        float4 kd = *(const float4*)(g_k + gpx*NUc + f4*4);
        float4 vd = *(const float4*)(g_v + gpx*NUc + f4*4);
        float* kdst = ks + (a*32 + c)*PITCH + f4*4;
        float* vdst = vs + (a*32 + c)*PITCH + f4*4;
        kdst[0]=kd.x; kdst[1]=kd.y; kdst[2]=kd.z; kdst[3]=kd.w;
        vdst[0]=vd.x; vdst[1]=vd.y; vdst[2]=vd.z; vdst[3]=vd.w;
    }
    __syncthreads();

    const int warp = tid / 32, lane = tid % 32;
    const int p = warp / NHh;          // pixel within tile 0..7
    const int n = warp % NHh;          // head
    const int j = j0 + p;
    const int sj = min(max(j - 12, 0), WW - KK);
    const int colbase = sj - sj_min;   // 0..7
    const int ra0 = si - i + (KK - 1);
    const int rc0 = sj - j + (KK - 1);
    const float* rp = rpb + n*49*49;

    float qr[HDd];
    {
        const float* qp = g_q + ((i*WW + j)*NUc + n*HDd);
        #pragma unroll
        for (int d = 0; d < HDd; d++) qr[d] = qp[d];
    }

    // pass 1: logits (+rpb), track max
    float lg[20];
    float lmax = -1e30f;
    #pragma unroll
    for (int e0 = 0; e0 < 20; e0++) {
        int e = lane + e0*32;
        if (e < KK*KK) {
            int a = e / KK, c = e % KK;
            const float* kp = ks + (a*32 + colbase + c)*PITCH + n*HDd;
            float acc = __ldg(rp + (ra0 + a)*49 + (rc0 + c));
            #pragma unroll
            for (int d = 0; d < HDd; d++) acc = fmaf(qr[d], kp[d], acc);
            lg[e0] = acc;
            lmax = fmaxf(lmax, acc);
        } else {
            lg[e0] = -1e30f;
        }
    }
    #pragma unroll
    for (int o = 16; o > 0; o >>= 1)
        lmax = fmaxf(lmax, __shfl_xor_sync(0xffffffffu, lmax, o));

    // pass 2: exp + weighted V accumulation
    float sum = 0.f;
    float oacc[HDd] = {0.f,0.f,0.f,0.f,0.f,0.f};
    #pragma unroll
    for (int e0 = 0; e0 < 20; e0++) {
        int e = lane + e0*32;
        if (e < KK*KK) {
            float pr = __expf(lg[e0] - lmax);
            sum += pr;
            int a = e / KK, c = e % KK;
            const float* vp = vs + (a*32 + colbase + c)*PITCH + n*HDd;
            #pragma unroll
            for (int d = 0; d < HDd; d++) oacc[d] = fmaf(pr, vp[d], oacc[d]);
        }
    }
    #pragma unroll
    for (int o = 16; o > 0; o >>= 1) {
        sum += __shfl_xor_sync(0xffffffffu, sum, o);
        #pragma unroll
        for (int d = 0; d < HDd; d++)
            oacc[d] += __shfl_xor_sync(0xffffffffu, oacc[d], o);
    }
    if (lane == 0) {
        float inv = 1.0f / sum;
        #pragma unroll
        for (int d = 0; d < HDd; d++) ao[p*NUc + n*HDd + d] = oacc[d]*inv;
    }
    __syncthreads();

    // fused output projection (24x24)
    if (tid < 8*NUc) {
        int pp = tid / NUc, oc = tid % NUc;
        float acc = __ldg(pb + oc);
        const float* wrow = pw + oc*NUc;
        #pragma unroll
        for (int ic = 0; ic < NUc; ic++)
            acc = fmaf(ao[pp*NUc + ic], __ldg(wrow + ic), acc);
        out[(i*WW + j0 + pp)*NUc + oc] = acc;
    }
}

// ---------------------------------------------------------------------------
// Final head: (24 -> 5) per pixel
// ---------------------------------------------------------------------------
__global__ void __launch_bounds__(128)
head_kernel(const float* __restrict__ x,
            const float* __restrict__ ow,   // (5,24)
            const float* __restrict__ ob,   // (5,)
            float* __restrict__ out)        // (64,88,5)
{
    int idx = blockIdx.x*blockDim.x + threadIdx.x;
    if (idx >= NPX*5) return;
    int px = idx / 5, oc = idx % 5;
    float acc = __ldg(ob + oc);
    const float* xr = x + px*NUc;
    const float* wr = ow + oc*NUc;
    #pragma unroll
    for (int c = 0; c < NUc; c++) acc = fmaf(__ldg(xr + c), __ldg(wr + c), acc);
    out[idx] = acc;
}

// ---------------------------------------------------------------------------
extern "C" void kernel_launch(void* const* d_in, const int* in_sizes, int n_in,
                              void* d_out, int out_size)
{
    const float* features  = (const float*)d_in[0];
    const int*   condition = (const int*)  d_in[1];
    const float* mask      = (const float*)d_in[2];
    const float* emb       = (const float*)d_in[3];
    const float* wih0      = (const float*)d_in[4];
    const float* whh0      = (const float*)d_in[5];
    const float* bih0      = (const float*)d_in[6];
    const float* bhh0      = (const float*)d_in[7];
    const float* wih1      = (const float*)d_in[8];
    const float* whh1      = (const float*)d_in[9];
    const float* bih1      = (const float*)d_in[10];
    const float* bhh1      = (const float*)d_in[11];
    const float* qkv_w     = (const float*)d_in[12];
    const float* qkv_b     = (const float*)d_in[13];
    const float* rpb       = (const float*)d_in[14];
    const float* proj_w    = (const float*)d_in[15];
    const float* proj_b    = (const float*)d_in[16];
    const float* out_w     = (const float*)d_in[17];
    const float* out_b     = (const float*)d_in[18];
    float* out = (float*)d_out;

    float *px0 = nullptr, *px1 = nullptr;
    cudaGetSymbolAddress((void**)&px0, g_x0);
    cudaGetSymbolAddress((void**)&px1, g_x1);

    const int natten_smem = (2*KK*32*PITCH + 8*NUc) * (int)sizeof(float); // 160768 B
    cudaFuncSetAttribute(natten_kernel,
                         cudaFuncAttributeMaxDynamicSharedMemorySize, natten_smem);

    // 1) fused LSTM
    lstm_kernel<<<WW, 96>>>(features, condition, mask, emb,
                            wih0, whh0, bih0, bhh0,
                            wih1, whh1, bih1, bhh1);

    dim3 ngrid(WW/8, TT);

    // 2) NATTEN layer 1
    qkv_kernel<<<66, 256>>>(px0, qkv_w, qkv_b);
    natten_kernel<<<ngrid, 1024, natten_smem>>>(rpb, proj_w, proj_b, px1);

    // 3) NATTEN layer 2
    qkv_kernel<<<66, 256>>>(px1, qkv_w, qkv_b);
    natten_kernel<<<ngrid, 1024, natten_smem>>>(rpb, proj_w, proj_b, px0);

    // 4) head
    head_kernel<<<(NPX*5 + 127)/128, 128>>>(px0, out_w, out_b, out);
}